// round 15
// baseline (speedup 1.0000x reference)
#include <cuda_runtime.h>
#include <cstdint>

#define Bb 8
#define Tt 2048
#define Cc 1024
#define Hh 64
#define NCHUNK_ITEMS 640   // (b, ib, j-chunk) items, chunks of <=8 j-tiles

__device__ float g_q[Bb * Tt * Hh];          // tf32-rounded q
__device__ float g_er[Tt * Hh];              // g_er[d][h] = tf32(E[T-1-d][h])
__device__ float g_pO[8 * 32 * 4 * 64 * 64];
__device__ float g_pml[8 * 32 * 4 * 128];    // [m(64) | l(64)] per chunk slot
__device__ int g_ctr;

__device__ __forceinline__ float cvt_tf32(float x) {
    uint32_t r;
    asm("cvt.rna.tf32.f32 %0, %1;" : "=r"(r) : "f"(x));
    return __uint_as_float(r);
}

__device__ __forceinline__ void mma8(float4& d, uint32_t a0, uint32_t a1,
                                     uint32_t a2, uint32_t a3,
                                     uint32_t b0, uint32_t b1) {
    asm volatile(
        "mma.sync.aligned.m16n8k8.row.col.f32.tf32.tf32.f32 "
        "{%0,%1,%2,%3}, {%4,%5,%6,%7}, {%8,%9}, {%0,%1,%2,%3};"
        : "+f"(d.x), "+f"(d.y), "+f"(d.z), "+f"(d.w)
        : "r"(a0), "r"(a1), "r"(a2), "r"(a3), "r"(b0), "r"(b1));
}

__device__ __forceinline__ void mma8f(float4& d, float a0, float a1,
                                      float a2, float a3, float b0, float b1) {
    mma8(d, __float_as_uint(a0), __float_as_uint(a1), __float_as_uint(a2),
         __float_as_uint(a3), __float_as_uint(b0), __float_as_uint(b1));
}

__device__ __forceinline__ void cp16(uint32_t smem_dst, const float* gsrc) {
    asm volatile("cp.async.ca.shared.global [%0], [%1], 16;\n"
                 :: "r"(smem_dst), "l"(gsrc));
}

// ---------------------------------------------------------------------------
// Kernel 1: q = x @ Wq via 3xTF32, cp.async double-buffered. BM=128.
// Preamble: each block writes its slice of g_er (reversed tf32 E table).
// W tiles loaded raw; hi/lo split happens at B-fragment read (bit-identical
// to a precomputed split). Epilogue stores q tf32-rounded.
// ---------------------------------------------------------------------------
#define QS_XS(st)  ((st) * 4608)            // 128*36
#define QS_WS(st)  (9216 + (st) * 2304)     // 32*72
#define QGEMM_SMEM_BYTES (13824 * 4)        // 55.3 KB

__global__ void __launch_bounds__(256, 2) qgemm_tf32(const float* __restrict__ x,
                                                     const float* __restrict__ w,
                                                     const float* __restrict__ E) {
    extern __shared__ float qs[];
    const int tid = threadIdx.x;
    if (blockIdx.x == 0 && tid == 0) g_ctr = 0;   // reset for attn work-steal

    // build g_er slice: 1024 elements per block (one float4 per thread)
    {
        const int base = blockIdx.x * 1024 + tid * 4;
        const int d = base >> 6, h = base & 63;
        const float4 v = *(const float4*)(E + (size_t)(Tt - 1 - d) * Hh + h);
        float4 o;
        o.x = cvt_tf32(v.x); o.y = cvt_tf32(v.y);
        o.z = cvt_tf32(v.z); o.w = cvt_tf32(v.w);
        *(float4*)(g_er + base) = o;
    }

    const int wid = tid >> 5, lane = tid & 31;
    const int gid = lane >> 2, tig = lane & 3;
    const int wr = wid & 3, wc = wid >> 2;
    const int r0 = blockIdx.x * 128;
    const uint32_t sbase = (uint32_t)__cvta_generic_to_shared(qs);

    auto issue_load = [&](int kb, int st) {
        const int k0g = kb * 32;
#pragma unroll
        for (int it = 0; it < 4; it++) {
            const int idx = tid + it * 256;
            const int row = idx >> 3, c4 = idx & 7;
            cp16(sbase + (QS_XS(st) + row * 36 + c4 * 4) * 4,
                 x + (size_t)(r0 + row) * Cc + k0g + c4 * 4);
        }
#pragma unroll
        for (int it = 0; it < 2; it++) {
            const int idx = tid + it * 256;
            const int kr = idx >> 4, c4 = idx & 15;
            cp16(sbase + (QS_WS(st) + kr * 72 + c4 * 4) * 4,
                 w + (size_t)(k0g + kr) * Hh + c4 * 4);
        }
    };

    float4 acc[2][4] = {};

    issue_load(0, 0);
    asm volatile("cp.async.commit_group;\n");

    for (int kb = 0; kb < Cc / 32; kb++) {
        if (kb + 1 < Cc / 32) {
            issue_load(kb + 1, (kb + 1) & 1);
            asm volatile("cp.async.commit_group;\n");
            asm volatile("cp.async.wait_group 1;\n");
        } else {
            asm volatile("cp.async.wait_group 0;\n");
        }
        __syncthreads();

        const float* Xs = qs + QS_XS(kb & 1);
        const float* Ws = qs + QS_WS(kb & 1);

#pragma unroll
        for (int kt = 0; kt < 4; kt++) {
            const int k0 = kt * 8;
            uint32_t ah[2][4], al[2][4];
#pragma unroll
            for (int m = 0; m < 2; m++)
#pragma unroll
                for (int p = 0; p < 4; p++) {
                    const int row = wr * 32 + m * 16 + gid + (p & 1) * 8;
                    const int col = k0 + tig + (p >> 1) * 4;
                    const float v = Xs[row * 36 + col];
                    const float h = cvt_tf32(v);
                    ah[m][p] = __float_as_uint(h);
                    al[m][p] = __float_as_uint(cvt_tf32(v - h));
                }
            uint32_t bh[4][2], bl[4][2];
#pragma unroll
            for (int nt = 0; nt < 4; nt++)
#pragma unroll
                for (int p = 0; p < 2; p++) {
                    const int ncol = wc * 32 + nt * 8 + gid;
                    const int krow = k0 + tig + 4 * p;
                    const float v = Ws[krow * 72 + ncol];
                    const float h = cvt_tf32(v);
                    bh[nt][p] = __float_as_uint(h);
                    bl[nt][p] = __float_as_uint(cvt_tf32(v - h));
                }
#pragma unroll
            for (int m = 0; m < 2; m++)
#pragma unroll
                for (int nt = 0; nt < 4; nt++) {
                    mma8(acc[m][nt], ah[m][0], ah[m][1], ah[m][2], ah[m][3],
                         bh[nt][0], bh[nt][1]);
                    mma8(acc[m][nt], al[m][0], al[m][1], al[m][2], al[m][3],
                         bh[nt][0], bh[nt][1]);
                    mma8(acc[m][nt], ah[m][0], ah[m][1], ah[m][2], ah[m][3],
                         bl[nt][0], bl[nt][1]);
                }
        }
        __syncthreads();
    }

#pragma unroll
    for (int m = 0; m < 2; m++)
#pragma unroll
        for (int nt = 0; nt < 4; nt++) {
            const int row = r0 + wr * 32 + m * 16 + gid;
            const int col = wc * 32 + nt * 8 + 2 * tig;
            *(float2*)(g_q + (size_t)row * Hh + col) =
                make_float2(cvt_tf32(acc[m][nt].x), cvt_tf32(acc[m][nt].y));
            *(float2*)(g_q + (size_t)(row + 8) * Hh + col) =
                make_float2(cvt_tf32(acc[m][nt].z), cvt_tf32(acc[m][nt].w));
        }
}

// ---------------------------------------------------------------------------
// Kernel 2: causal flash attention + rel bias (exact R13 config, best known).
// 4 warps, 32 rows x 32 j each; Eb double-buffered smem, shared R ring,
// per-half softmax, cp.async double buffering, split-j chunks + merge kernel.
// ---------------------------------------------------------------------------
#define KST 68
#define RST 132
#define OFF_KS0 0
#define OFF_KS1 4352
#define OFF_EB0 8704
#define OFF_EB1 13056
#define OFF_RS  17408
#define OFF_LP  25856
#define OFF_MM  25984
#define OFF_WA  26112
#define OFF_WB  26176
#define OFF_IV  26240
#define SMEMF   26304
#define ATTN_SMEM_BYTES (SMEMF * 4)
#define NEGINF __int_as_float(0xff800000)

__global__ void __launch_bounds__(128, 2) attn_mma(float* __restrict__ out) {
    extern __shared__ float sm[];
    __shared__ int s_item;

    const int tid = threadIdx.x;
    const int wid = tid >> 5, lane = tid & 31;
    const int gid = lane >> 2, tig = lane & 3;
    const int wr = wid & 1, wc = wid >> 1;
    const int mr = wr * 32;       // warp's 32 rows
    const int nc = wc * 32;       // warp's j-half base
    const uint32_t sbase = (uint32_t)__cvta_generic_to_shared(sm);
    const unsigned FULL = 0xffffffffu;
    const int srcA = (lane & ~3) | (tig >> 1);
    const int srcB = srcA + 2;
    const bool oddt = (tig & 1);

    while (true) {
        __syncthreads();
        if (tid == 0) s_item = atomicAdd(&g_ctr, 1);
        __syncthreads();
        const int item = s_item;
        if (item >= NCHUNK_ITEMS) return;

        const int b = item & 7;
        int t = item >> 3;
        int ib = 31;
        while (true) {
            const int n = (ib >> 3) + 1;
            if (t < n) break;
            t -= n;
            ib--;
        }
        const int chunk = t;
        const int s0c = chunk * 8;
        const int s1c = min(s0c + 7, ib);
        const int nch = (ib >> 3) + 1;
        const int i0 = ib * 64;
        const float* qb = g_q + (size_t)b * (Tt * Hh);

        auto issue_tile = [&](int s) {
            const int j0t = (ib - s) * 64;
            const int dft = s * 64;
            const uint32_t kdst = sbase + (OFF_KS0 + (s & 1) * 4352) * 4;
            const uint32_t edst = sbase + (OFF_EB0 + (s & 1) * 4352) * 4;
#pragma unroll
            for (int it = 0; it < 8; it++) {
                const int idx = tid + it * 128;
                const int row = idx >> 4, c4 = idx & 15;
                cp16(kdst + (row * KST + c4 * 4) * 4,
                     qb + (size_t)(j0t + row) * Hh + c4 * 4);
                cp16(edst + (row * KST + c4 * 4) * 4,
                     g_er + (size_t)(dft + row) * Hh + c4 * 4);
            }
            asm volatile("cp.async.commit_group;\n");
        };

        issue_tile(s0c);   // prefetch first tile

        // Q fragments -> registers, pre-scaled by H^-0.5 (exact pow2 in tf32)
        uint32_t qa[2][8][4];
#pragma unroll
        for (int m = 0; m < 2; m++) {
            const int row0 = i0 + mr + m * 16 + gid;
#pragma unroll
            for (int kt = 0; kt < 8; kt++) {
                const int k0 = kt * 8 + tig;
                qa[m][kt][0] = __float_as_uint(0.125f * qb[(size_t)row0 * Hh + k0]);
                qa[m][kt][1] = __float_as_uint(0.125f * qb[(size_t)(row0 + 8) * Hh + k0]);
                qa[m][kt][2] = __float_as_uint(0.125f * qb[(size_t)row0 * Hh + k0 + 4]);
                qa[m][kt][3] = __float_as_uint(0.125f * qb[(size_t)(row0 + 8) * Hh + k0 + 4]);
            }
        }

        if (s0c == 0) {
            // zero ring cols 64..127 (covers dg<0 at the diagonal tile)
#pragma unroll
            for (int it = 0; it < 8; it++) {
                const int idx = tid + it * 128;
                const int row = idx >> 4, c4 = idx & 15;
                *(float4*)(sm + OFF_RS + row * RST + 64 + c4 * 4) =
                    make_float4(0.f, 0.f, 0.f, 0.f);
            }
        } else {
            // prologue R block for diffp = (s0c-1)*64; E from g_er (one-time)
            const int diffp = (s0c - 1) * 64;
            float4 racc[2][4] = {};
#pragma unroll
            for (int kt = 0; kt < 8; kt++) {
                const int k0 = kt * 8;
#pragma unroll
                for (int nt = 0; nt < 4; nt++) {
                    const int rr = nc + nt * 8 + gid;
                    const float* er = g_er + (size_t)(diffp + rr) * Hh;
                    const float b0 = er[k0 + tig], b1 = er[k0 + tig + 4];
#pragma unroll
                    for (int m = 0; m < 2; m++)
                        mma8f(racc[m][nt],
                              __uint_as_float(qa[m][kt][0]), __uint_as_float(qa[m][kt][1]),
                              __uint_as_float(qa[m][kt][2]), __uint_as_float(qa[m][kt][3]),
                              b0, b1);
                }
            }
            const int rb = diffp & 127;   // = 64
#pragma unroll
            for (int m = 0; m < 2; m++)
#pragma unroll
                for (int nt = 0; nt < 4; nt++) {
                    const int colr = rb + nc + nt * 8 + 2 * tig;
                    const int rw = mr + m * 16 + gid;
                    *(float2*)(sm + OFF_RS + rw * RST + colr) =
                        make_float2(racc[m][nt].x, racc[m][nt].y);
                    *(float2*)(sm + OFF_RS + (rw + 8) * RST + colr) =
                        make_float2(racc[m][nt].z, racc[m][nt].w);
                }
        }

        float4 oacc[2][8] = {};
        float ma[2][2] = {{-1e30f, -1e30f}, {-1e30f, -1e30f}};
        float la[2][2] = {{0.f, 0.f}, {0.f, 0.f}};

        for (int s = s0c; s <= s1c; s++) {
            const int diff = 64 * s;

            asm volatile("cp.async.wait_group 0;\n");
            __syncthreads();   // tile buffers visible; prev-tile readers done
            if (s < s1c) issue_tile(s + 1);

            const float* Ks = sm + ((s & 1) ? OFF_KS1 : OFF_KS0);
            const float* Eb = sm + ((s & 1) ? OFF_EB1 : OFF_EB0);

            // R (new 64 dg cols; warp: rows mr..+31 x cols nc..+31)
            float4 racc[2][4] = {};
#pragma unroll
            for (int kt = 0; kt < 8; kt++) {
                const int k0 = kt * 8;
#pragma unroll
                for (int nt = 0; nt < 4; nt++) {
                    const int rr = nc + nt * 8 + gid;
                    const float b0 = Eb[rr * KST + k0 + tig];
                    const float b1 = Eb[rr * KST + k0 + tig + 4];
#pragma unroll
                    for (int m = 0; m < 2; m++)
                        mma8f(racc[m][nt],
                              __uint_as_float(qa[m][kt][0]), __uint_as_float(qa[m][kt][1]),
                              __uint_as_float(qa[m][kt][2]), __uint_as_float(qa[m][kt][3]),
                              b0, b1);
                }
            }
            {
                const int rb = diff & 127;
#pragma unroll
                for (int m = 0; m < 2; m++)
#pragma unroll
                    for (int nt = 0; nt < 4; nt++) {
                        const int colr = rb + nc + nt * 8 + 2 * tig;
                        const int rw = mr + m * 16 + gid;
                        *(float2*)(sm + OFF_RS + rw * RST + colr) =
                            make_float2(racc[m][nt].x, racc[m][nt].y);
                        *(float2*)(sm + OFF_RS + (rw + 8) * RST + colr) =
                            make_float2(racc[m][nt].z, racc[m][nt].w);
                    }
            }

            // S = Q @ K^T (own j-half; B-frags reused across both m)
            float4 sacc[2][4] = {};
#pragma unroll
            for (int kt = 0; kt < 8; kt++) {
                const int k0 = kt * 8;
#pragma unroll
                for (int nt = 0; nt < 4; nt++) {
                    const int jr = nc + nt * 8 + gid;
                    const float b0 = Ks[jr * KST + k0 + tig];
                    const float b1 = Ks[jr * KST + k0 + tig + 4];
#pragma unroll
                    for (int m = 0; m < 2; m++)
                        mma8f(sacc[m][nt],
                              __uint_as_float(qa[m][kt][0]), __uint_as_float(qa[m][kt][1]),
                              __uint_as_float(qa[m][kt][2]), __uint_as_float(qa[m][kt][3]),
                              b0, b1);
                }
            }
            __syncthreads();   // Rs new block visible to all warps

            // gather (pre-scaled) + mask on diagonal; per-half per-m softmax
#pragma unroll
            for (int m = 0; m < 2; m++) {
                const int r0l = mr + m * 16 + gid, r1l = r0l + 8;
                float mt0 = NEGINF, mt1 = NEGINF;
#pragma unroll
                for (int nt = 0; nt < 4; nt++) {
                    const int c0 = nc + nt * 8 + 2 * tig, c1 = c0 + 1;
                    float s00 = sacc[m][nt].x + sm[OFF_RS + r0l * RST + ((diff + r0l - c0) & 127)];
                    float s01 = sacc[m][nt].y + sm[OFF_RS + r0l * RST + ((diff + r0l - c1) & 127)];
                    float s10 = sacc[m][nt].z + sm[OFF_RS + r1l * RST + ((diff + r1l - c0) & 127)];
                    float s11 = sacc[m][nt].w + sm[OFF_RS + r1l * RST + ((diff + r1l - c1) & 127)];
                    if (s == 0) {
                        if (c0 > r0l) s00 = NEGINF;
                        if (c1 > r0l) s01 = NEGINF;
                        if (c0 > r1l) s10 = NEGINF;
                        if (c1 > r1l) s11 = NEGINF;
                    }
                    sacc[m][nt] = make_float4(s00, s01, s10, s11);
                    mt0 = fmaxf(mt0, fmaxf(s00, s01));
                    mt1 = fmaxf(mt1, fmaxf(s10, s11));
                }
                mt0 = fmaxf(mt0, __shfl_xor_sync(FULL, mt0, 1));
                mt0 = fmaxf(mt0, __shfl_xor_sync(FULL, mt0, 2));
                mt1 = fmaxf(mt1, __shfl_xor_sync(FULL, mt1, 1));
                mt1 = fmaxf(mt1, __shfl_xor_sync(FULL, mt1, 2));
                const float mn0 = fmaxf(ma[m][0], mt0);
                const float mn1 = fmaxf(ma[m][1], mt1);

                float sum0 = 0.f, sum1 = 0.f;
#pragma unroll
                for (int nt = 0; nt < 4; nt++) {
                    const float p00 = cvt_tf32(__expf(sacc[m][nt].x - mn0));
                    const float p01 = cvt_tf32(__expf(sacc[m][nt].y - mn0));
                    const float p10 = cvt_tf32(__expf(sacc[m][nt].z - mn1));
                    const float p11 = cvt_tf32(__expf(sacc[m][nt].w - mn1));
                    sum0 += p00 + p01;
                    sum1 += p10 + p11;
                    sacc[m][nt] = make_float4(p00, p01, p10, p11);
                }
                sum0 += __shfl_xor_sync(FULL, sum0, 1);
                sum0 += __shfl_xor_sync(FULL, sum0, 2);
                sum1 += __shfl_xor_sync(FULL, sum1, 1);
                sum1 += __shfl_xor_sync(FULL, sum1, 2);
                const float corr0 = __expf(ma[m][0] - mn0);
                const float corr1 = __expf(ma[m][1] - mn1);
                ma[m][0] = mn0; ma[m][1] = mn1;
                la[m][0] = la[m][0] * corr0 + sum0;
                la[m][1] = la[m][1] * corr1 + sum1;
#pragma unroll
                for (int nt = 0; nt < 8; nt++) {
                    oacc[m][nt].x *= corr0; oacc[m][nt].y *= corr0;
                    oacc[m][nt].z *= corr1; oacc[m][nt].w *= corr1;
                }
            }

            // O += P @ V (own j-half, all 64 h); B-frags reused across m
#pragma unroll
            for (int kt = 0; kt < 4; kt++) {
                float A0[2], A1[2], A2[2], A3[2];
#pragma unroll
                for (int m = 0; m < 2; m++) {
                    const float p00 = sacc[m][kt].x, p01 = sacc[m][kt].y;
                    const float p10 = sacc[m][kt].z, p11 = sacc[m][kt].w;
                    const float e0 = __shfl_sync(FULL, p00, srcA);
                    const float e1 = __shfl_sync(FULL, p01, srcA);
                    const float f0 = __shfl_sync(FULL, p00, srcB);
                    const float f1 = __shfl_sync(FULL, p01, srcB);
                    const float g0 = __shfl_sync(FULL, p10, srcA);
                    const float g1 = __shfl_sync(FULL, p11, srcA);
                    const float h0 = __shfl_sync(FULL, p10, srcB);
                    const float h1 = __shfl_sync(FULL, p11, srcB);
                    A0[m] = oddt ? e1 : e0;
                    A1[m] = oddt ? g1 : g0;
                    A2[m] = oddt ? f1 : f0;
                    A3[m] = oddt ? h1 : h0;
                }
                const int kr0 = nc + kt * 8 + tig;
#pragma unroll
                for (int nto = 0; nto < 8; nto++) {
                    const int hcol = nto * 8 + gid;
                    const float b0 = Ks[kr0 * KST + hcol];
                    const float b1 = Ks[(kr0 + 4) * KST + hcol];
#pragma unroll
                    for (int m = 0; m < 2; m++)
                        mma8f(oacc[m][nto], A0[m], A1[m], A2[m], A3[m], b0, b1);
                }
            }
        }

        // ---- item epilogue: LSE-combine the two j-halves via smem scratch ----
        __syncthreads();   // all PV reads of Ks/Rs done; reuse Rs as scratch
#pragma unroll
        for (int m = 0; m < 2; m++) {
            const int rw = mr + m * 16 + gid;
#pragma unroll
            for (int nto = 0; nto < 8; nto++) {
                const int col = nto * 8 + 2 * tig;
                *(float2*)(sm + OFF_RS + wc * 4096 + rw * 64 + col) =
                    make_float2(oacc[m][nto].x, oacc[m][nto].y);
                *(float2*)(sm + OFF_RS + wc * 4096 + (rw + 8) * 64 + col) =
                    make_float2(oacc[m][nto].z, oacc[m][nto].w);
            }
            if (tig == 0) {
                sm[OFF_LP + wc * 64 + rw] = la[m][0];
                sm[OFF_LP + wc * 64 + rw + 8] = la[m][1];
                sm[OFF_MM + wc * 64 + rw] = ma[m][0];
                sm[OFF_MM + wc * 64 + rw + 8] = ma[m][1];
            }
        }
        __syncthreads();

        if (wc == 0) {
            const int slot = (b * 32 + ib) * 4 + chunk;
            float* po = g_pO + (size_t)slot * 4096;
            float* pml = g_pml + (size_t)slot * 128;
            {
                const int row = mr + lane;   // 32 lanes <-> 32 rows
                const float mA = sm[OFF_MM + row], mB = sm[OFF_MM + 64 + row];
                const float M = fmaxf(mA, mB);
                const float wA = __expf(mA - M), wB = __expf(mB - M);
                const float L = wA * sm[OFF_LP + row] + wB * sm[OFF_LP + 64 + row];
                sm[OFF_WA + row] = wA;
                sm[OFF_WB + row] = wB;
                sm[OFF_IV + row] = 1.0f / L;
                if (nch > 1) {
                    pml[row] = M;
                    pml[64 + row] = L;
                }
            }
            __syncwarp();
#pragma unroll
            for (int it = 0; it < 16; it++) {
                const int idx = lane + it * 32;   // 512 float4 over 32 rows
                const int rl = idx >> 4, c4 = idx & 15;
                const int row = mr + rl;
                const float4 A = *(const float4*)(sm + OFF_RS + row * 64 + c4 * 4);
                const float4 Bv = *(const float4*)(sm + OFF_RS + 4096 + row * 64 + c4 * 4);
                const float wA = sm[OFF_WA + row], wB = sm[OFF_WB + row];
                const float vx = wA * A.x + wB * Bv.x;
                const float vy = wA * A.y + wB * Bv.y;
                const float vz = wA * A.z + wB * Bv.z;
                const float vw = wA * A.w + wB * Bv.w;
                if (nch == 1) {
                    const float inv = sm[OFF_IV + row];
                    *(float4*)(out + ((size_t)b * Tt + i0 + row) * Hh + c4 * 4) =
                        make_float4(vx * inv, vy * inv, vz * inv, vw * inv);
                } else {
                    *(float4*)(po + row * 64 + c4 * 4) = make_float4(vx, vy, vz, vw);
                }
            }
        }
    }
}

// ---------------------------------------------------------------------------
// Kernel 3: merge split-j partials (ib >= 8 only); nch slots per (b,ib).
// ---------------------------------------------------------------------------
__global__ void __launch_bounds__(256) merge_kernel(float* __restrict__ out) {
    __shared__ float swgt[4][16];
    __shared__ float sinv[16];

    const int blk = blockIdx.x;             // 0..767
    const int itemi = blk >> 2, qtr = blk & 3;
    const int b = itemi / 24;
    const int ib = 8 + itemi % 24;
    const int nch = (ib >> 3) + 1;
    const int tid = threadIdx.x;
    const float* pml = g_pml + (size_t)((b * 32 + ib) * 4) * 128;
    const float* po = g_pO + (size_t)((b * 32 + ib) * 4) * 4096;
    float* ob = out + ((size_t)b * Tt + ib * 64) * Hh;

    if (tid < 16) {
        const int row = qtr * 16 + tid;
        float M = -1e30f;
        for (int c = 0; c < nch; c++) M = fmaxf(M, pml[c * 128 + row]);
        float L = 0.f;
        for (int c = 0; c < nch; c++) {
            const float w = __expf(pml[c * 128 + row] - M);
            swgt[c][tid] = w;
            L += w * pml[c * 128 + 64 + row];
        }
        sinv[tid] = 1.0f / L;
    }
    __syncthreads();

    const int rl = tid >> 4, c4 = tid & 15;
    const int row = qtr * 16 + rl;
    float4 v = make_float4(0.f, 0.f, 0.f, 0.f);
    for (int c = 0; c < nch; c++) {
        const float w = swgt[c][rl];
        const float4 p = *(const float4*)(po + (size_t)c * 4096 + row * 64 + c4 * 4);
        v.x += w * p.x; v.y += w * p.y; v.z += w * p.z; v.w += w * p.w;
    }
    const float inv = sinv[rl];
    *(float4*)(ob + (size_t)row * Hh + c4 * 4) =
        make_float4(v.x * inv, v.y * inv, v.z * inv, v.w * inv);
}

// ---------------------------------------------------------------------------
extern "C" void kernel_launch(void* const* d_in, const int* in_sizes, int n_in,
                              void* d_out, int out_size) {
    const float* x  = (const float*)d_in[0];   // [8, 2048, 1024]
    const float* Wq = (const float*)d_in[1];   // [1024, 64]
    const float* E  = (const float*)d_in[2];   // [2048, 64]
    float* out = (float*)d_out;                // [8, 2048, 64]

    cudaFuncSetAttribute(qgemm_tf32, cudaFuncAttributeMaxDynamicSharedMemorySize,
                         QGEMM_SMEM_BYTES);
    cudaFuncSetAttribute(attn_mma, cudaFuncAttributeMaxDynamicSharedMemorySize,
                         ATTN_SMEM_BYTES);

    qgemm_tf32<<<(Bb * Tt) / 128, 256, QGEMM_SMEM_BYTES>>>(x, Wq, E);  // + g_er
    attn_mma<<<296, 128, ATTN_SMEM_BYTES>>>(out);
    merge_kernel<<<768, 256>>>(out);
}

// round 16
// speedup vs baseline: 1.0131x; 1.0131x over previous
#include <cuda_runtime.h>
#include <cstdint>

#define Bb 8
#define Tt 2048
#define Cc 1024
#define Hh 64
#define NCHUNK_ITEMS 640   // (b, ib, j-chunk) items, chunks of <=8 j-tiles

__device__ float g_q[Bb * Tt * Hh];          // tf32-rounded q
__device__ float g_wh[Cc * Hh];
__device__ float g_wl[Cc * Hh];
__device__ float g_er[Tt * Hh];              // g_er[d][h] = tf32(E[T-1-d][h])
__device__ float g_pO[8 * 32 * 4 * 64 * 64];
__device__ float g_pml[8 * 32 * 4 * 128];    // [m(64) | l(64)] per chunk slot
__device__ int g_ctr;

__device__ __forceinline__ float cvt_tf32(float x) {
    uint32_t r;
    asm("cvt.rna.tf32.f32 %0, %1;" : "=r"(r) : "f"(x));
    return __uint_as_float(r);
}

__device__ __forceinline__ void mma8(float4& d, uint32_t a0, uint32_t a1,
                                     uint32_t a2, uint32_t a3,
                                     uint32_t b0, uint32_t b1) {
    asm volatile(
        "mma.sync.aligned.m16n8k8.row.col.f32.tf32.tf32.f32 "
        "{%0,%1,%2,%3}, {%4,%5,%6,%7}, {%8,%9}, {%0,%1,%2,%3};"
        : "+f"(d.x), "+f"(d.y), "+f"(d.z), "+f"(d.w)
        : "r"(a0), "r"(a1), "r"(a2), "r"(a3), "r"(b0), "r"(b1));
}

__device__ __forceinline__ void mma8f(float4& d, float a0, float a1,
                                      float a2, float a3, float b0, float b1) {
    mma8(d, __float_as_uint(a0), __float_as_uint(a1), __float_as_uint(a2),
         __float_as_uint(a3), __float_as_uint(b0), __float_as_uint(b1));
}

__device__ __forceinline__ void cp16(uint32_t smem_dst, const float* gsrc) {
    asm volatile("cp.async.ca.shared.global [%0], [%1], 16;\n"
                 :: "r"(smem_dst), "l"(gsrc));
}

// ---------------------------------------------------------------------------
// Kernel 0: split Wq into tf32 hi/lo; build reversed tf32-rounded E table.
// ---------------------------------------------------------------------------
__global__ void wconv_kernel(const float* __restrict__ w,
                             const float* __restrict__ E) {
    const int i = blockIdx.x * 256 + threadIdx.x;
    if (i < Cc * Hh) {
        const float v = w[i];
        const float h = cvt_tf32(v);
        g_wh[i] = h;
        g_wl[i] = cvt_tf32(v - h);
    }
    if (i < Tt * Hh) {
        const int d = i >> 6, hcol = i & 63;
        g_er[i] = cvt_tf32(E[(size_t)(Tt - 1 - d) * Hh + hcol]);
    }
}

// ---------------------------------------------------------------------------
// Kernel 1: q = x @ Wq via 3xTF32, cp.async double-buffered.
// BM=64 -> grid 256, 2 CTAs/SM (16 warps/SM): fixes the measured occupancy
// hole (R15 ncu: grid=128, occ 12.4%, 20 SMs idle). Wh/Wl precomputed.
// Epilogue stores q tf32-rounded.
// ---------------------------------------------------------------------------
#define QS_XS(st)  ((st) * 2304)            // 64*36
#define QS_WH(st)  (4608 + (st) * 2304)     // 32*72
#define QS_WL(st)  (9216 + (st) * 2304)
#define QGEMM_SMEM_BYTES (13824 * 4)        // 55.3 KB -> 2 CTAs/SM

__global__ void __launch_bounds__(256, 2) qgemm_tf32(const float* __restrict__ x) {
    extern __shared__ float qs[];
    const int tid = threadIdx.x;
    if (blockIdx.x == 0 && tid == 0) g_ctr = 0;   // reset for attn work-steal

    const int wid = tid >> 5, lane = tid & 31;
    const int gid = lane >> 2, tig = lane & 3;
    const int wr = wid & 3, wc = wid >> 2;
    const int r0 = blockIdx.x * 64;
    const uint32_t sbase = (uint32_t)__cvta_generic_to_shared(qs);

    auto issue_load = [&](int kb, int st) {
        const int k0g = kb * 32;
#pragma unroll
        for (int it = 0; it < 2; it++) {
            const int idx = tid + it * 256;     // 512 float4
            const int row = idx >> 3, c4 = idx & 7;
            cp16(sbase + (QS_XS(st) + row * 36 + c4 * 4) * 4,
                 x + (size_t)(r0 + row) * Cc + k0g + c4 * 4);
        }
#pragma unroll
        for (int it = 0; it < 2; it++) {
            const int idx = tid + it * 256;
            const int kr = idx >> 4, c4 = idx & 15;
            cp16(sbase + (QS_WH(st) + kr * 72 + c4 * 4) * 4,
                 g_wh + (size_t)(k0g + kr) * Hh + c4 * 4);
            cp16(sbase + (QS_WL(st) + kr * 72 + c4 * 4) * 4,
                 g_wl + (size_t)(k0g + kr) * Hh + c4 * 4);
        }
    };

    float4 acc[4] = {};

    issue_load(0, 0);
    asm volatile("cp.async.commit_group;\n");

    for (int kb = 0; kb < Cc / 32; kb++) {
        if (kb + 1 < Cc / 32) {
            issue_load(kb + 1, (kb + 1) & 1);
            asm volatile("cp.async.commit_group;\n");
            asm volatile("cp.async.wait_group 1;\n");
        } else {
            asm volatile("cp.async.wait_group 0;\n");
        }
        __syncthreads();

        const float* Xs = qs + QS_XS(kb & 1);
        const float* Wh = qs + QS_WH(kb & 1);
        const float* Wl = qs + QS_WL(kb & 1);

#pragma unroll
        for (int kt = 0; kt < 4; kt++) {
            const int k0 = kt * 8;
            uint32_t ah[4], al[4];
#pragma unroll
            for (int p = 0; p < 4; p++) {
                const int row = wr * 16 + gid + (p & 1) * 8;
                const int col = k0 + tig + (p >> 1) * 4;
                const float v = Xs[row * 36 + col];
                const float h = cvt_tf32(v);
                ah[p] = __float_as_uint(h);
                al[p] = __float_as_uint(cvt_tf32(v - h));
            }
            uint32_t bh[4][2], bl[4][2];
#pragma unroll
            for (int nt = 0; nt < 4; nt++)
#pragma unroll
                for (int p = 0; p < 2; p++) {
                    const int ncol = wc * 32 + nt * 8 + gid;
                    const int krow = k0 + tig + 4 * p;
                    bh[nt][p] = __float_as_uint(Wh[krow * 72 + ncol]);
                    bl[nt][p] = __float_as_uint(Wl[krow * 72 + ncol]);
                }
#pragma unroll
            for (int nt = 0; nt < 4; nt++) {
                mma8(acc[nt], ah[0], ah[1], ah[2], ah[3], bh[nt][0], bh[nt][1]);
                mma8(acc[nt], al[0], al[1], al[2], al[3], bh[nt][0], bh[nt][1]);
                mma8(acc[nt], ah[0], ah[1], ah[2], ah[3], bl[nt][0], bl[nt][1]);
            }
        }
        __syncthreads();
    }

#pragma unroll
    for (int nt = 0; nt < 4; nt++) {
        const int row = r0 + wr * 16 + gid;
        const int col = wc * 32 + nt * 8 + 2 * tig;
        *(float2*)(g_q + (size_t)row * Hh + col) =
            make_float2(cvt_tf32(acc[nt].x), cvt_tf32(acc[nt].y));
        *(float2*)(g_q + (size_t)(row + 8) * Hh + col) =
            make_float2(cvt_tf32(acc[nt].z), cvt_tf32(acc[nt].w));
    }
}

// ---------------------------------------------------------------------------
// Kernel 2: causal flash attention + rel bias (exact R13 config, best known).
// 4 warps, 32 rows x 32 j each; Eb double-buffered smem, shared R ring,
// per-half softmax, cp.async double buffering, split-j chunks + merge kernel.
// ---------------------------------------------------------------------------
#define KST 68
#define RST 132
#define OFF_KS0 0
#define OFF_KS1 4352
#define OFF_EB0 8704
#define OFF_EB1 13056
#define OFF_RS  17408
#define OFF_LP  25856
#define OFF_MM  25984
#define OFF_WA  26112
#define OFF_WB  26176
#define OFF_IV  26240
#define SMEMF   26304
#define ATTN_SMEM_BYTES (SMEMF * 4)
#define NEGINF __int_as_float(0xff800000)

__global__ void __launch_bounds__(128, 2) attn_mma(float* __restrict__ out) {
    extern __shared__ float sm[];
    __shared__ int s_item;

    const int tid = threadIdx.x;
    const int wid = tid >> 5, lane = tid & 31;
    const int gid = lane >> 2, tig = lane & 3;
    const int wr = wid & 1, wc = wid >> 1;
    const int mr = wr * 32;       // warp's 32 rows
    const int nc = wc * 32;       // warp's j-half base
    const uint32_t sbase = (uint32_t)__cvta_generic_to_shared(sm);
    const unsigned FULL = 0xffffffffu;
    const int srcA = (lane & ~3) | (tig >> 1);
    const int srcB = srcA + 2;
    const bool oddt = (tig & 1);

    while (true) {
        __syncthreads();
        if (tid == 0) s_item = atomicAdd(&g_ctr, 1);
        __syncthreads();
        const int item = s_item;
        if (item >= NCHUNK_ITEMS) return;

        const int b = item & 7;
        int t = item >> 3;
        int ib = 31;
        while (true) {
            const int n = (ib >> 3) + 1;
            if (t < n) break;
            t -= n;
            ib--;
        }
        const int chunk = t;
        const int s0c = chunk * 8;
        const int s1c = min(s0c + 7, ib);
        const int nch = (ib >> 3) + 1;
        const int i0 = ib * 64;
        const float* qb = g_q + (size_t)b * (Tt * Hh);

        auto issue_tile = [&](int s) {
            const int j0t = (ib - s) * 64;
            const int dft = s * 64;
            const uint32_t kdst = sbase + (OFF_KS0 + (s & 1) * 4352) * 4;
            const uint32_t edst = sbase + (OFF_EB0 + (s & 1) * 4352) * 4;
#pragma unroll
            for (int it = 0; it < 8; it++) {
                const int idx = tid + it * 128;
                const int row = idx >> 4, c4 = idx & 15;
                cp16(kdst + (row * KST + c4 * 4) * 4,
                     qb + (size_t)(j0t + row) * Hh + c4 * 4);
                cp16(edst + (row * KST + c4 * 4) * 4,
                     g_er + (size_t)(dft + row) * Hh + c4 * 4);
            }
            asm volatile("cp.async.commit_group;\n");
        };

        issue_tile(s0c);   // prefetch first tile

        // Q fragments -> registers, pre-scaled by H^-0.5 (exact pow2 in tf32)
        uint32_t qa[2][8][4];
#pragma unroll
        for (int m = 0; m < 2; m++) {
            const int row0 = i0 + mr + m * 16 + gid;
#pragma unroll
            for (int kt = 0; kt < 8; kt++) {
                const int k0 = kt * 8 + tig;
                qa[m][kt][0] = __float_as_uint(0.125f * qb[(size_t)row0 * Hh + k0]);
                qa[m][kt][1] = __float_as_uint(0.125f * qb[(size_t)(row0 + 8) * Hh + k0]);
                qa[m][kt][2] = __float_as_uint(0.125f * qb[(size_t)row0 * Hh + k0 + 4]);
                qa[m][kt][3] = __float_as_uint(0.125f * qb[(size_t)(row0 + 8) * Hh + k0 + 4]);
            }
        }

        if (s0c == 0) {
            // zero ring cols 64..127 (covers dg<0 at the diagonal tile)
#pragma unroll
            for (int it = 0; it < 8; it++) {
                const int idx = tid + it * 128;
                const int row = idx >> 4, c4 = idx & 15;
                *(float4*)(sm + OFF_RS + row * RST + 64 + c4 * 4) =
                    make_float4(0.f, 0.f, 0.f, 0.f);
            }
        } else {
            // prologue R block for diffp = (s0c-1)*64; E from g_er (one-time)
            const int diffp = (s0c - 1) * 64;
            float4 racc[2][4] = {};
#pragma unroll
            for (int kt = 0; kt < 8; kt++) {
                const int k0 = kt * 8;
#pragma unroll
                for (int nt = 0; nt < 4; nt++) {
                    const int rr = nc + nt * 8 + gid;
                    const float* er = g_er + (size_t)(diffp + rr) * Hh;
                    const float b0 = er[k0 + tig], b1 = er[k0 + tig + 4];
#pragma unroll
                    for (int m = 0; m < 2; m++)
                        mma8f(racc[m][nt],
                              __uint_as_float(qa[m][kt][0]), __uint_as_float(qa[m][kt][1]),
                              __uint_as_float(qa[m][kt][2]), __uint_as_float(qa[m][kt][3]),
                              b0, b1);
                }
            }
            const int rb = diffp & 127;   // = 64
#pragma unroll
            for (int m = 0; m < 2; m++)
#pragma unroll
                for (int nt = 0; nt < 4; nt++) {
                    const int colr = rb + nc + nt * 8 + 2 * tig;
                    const int rw = mr + m * 16 + gid;
                    *(float2*)(sm + OFF_RS + rw * RST + colr) =
                        make_float2(racc[m][nt].x, racc[m][nt].y);
                    *(float2*)(sm + OFF_RS + (rw + 8) * RST + colr) =
                        make_float2(racc[m][nt].z, racc[m][nt].w);
                }
        }

        float4 oacc[2][8] = {};
        float ma[2][2] = {{-1e30f, -1e30f}, {-1e30f, -1e30f}};
        float la[2][2] = {{0.f, 0.f}, {0.f, 0.f}};

        for (int s = s0c; s <= s1c; s++) {
            const int diff = 64 * s;

            asm volatile("cp.async.wait_group 0;\n");
            __syncthreads();   // tile buffers visible; prev-tile readers done
            if (s < s1c) issue_tile(s + 1);

            const float* Ks = sm + ((s & 1) ? OFF_KS1 : OFF_KS0);
            const float* Eb = sm + ((s & 1) ? OFF_EB1 : OFF_EB0);

            // R (new 64 dg cols; warp: rows mr..+31 x cols nc..+31)
            float4 racc[2][4] = {};
#pragma unroll
            for (int kt = 0; kt < 8; kt++) {
                const int k0 = kt * 8;
#pragma unroll
                for (int nt = 0; nt < 4; nt++) {
                    const int rr = nc + nt * 8 + gid;
                    const float b0 = Eb[rr * KST + k0 + tig];
                    const float b1 = Eb[rr * KST + k0 + tig + 4];
#pragma unroll
                    for (int m = 0; m < 2; m++)
                        mma8f(racc[m][nt],
                              __uint_as_float(qa[m][kt][0]), __uint_as_float(qa[m][kt][1]),
                              __uint_as_float(qa[m][kt][2]), __uint_as_float(qa[m][kt][3]),
                              b0, b1);
                }
            }
            {
                const int rb = diff & 127;
#pragma unroll
                for (int m = 0; m < 2; m++)
#pragma unroll
                    for (int nt = 0; nt < 4; nt++) {
                        const int colr = rb + nc + nt * 8 + 2 * tig;
                        const int rw = mr + m * 16 + gid;
                        *(float2*)(sm + OFF_RS + rw * RST + colr) =
                            make_float2(racc[m][nt].x, racc[m][nt].y);
                        *(float2*)(sm + OFF_RS + (rw + 8) * RST + colr) =
                            make_float2(racc[m][nt].z, racc[m][nt].w);
                    }
            }

            // S = Q @ K^T (own j-half; B-frags reused across both m)
            float4 sacc[2][4] = {};
#pragma unroll
            for (int kt = 0; kt < 8; kt++) {
                const int k0 = kt * 8;
#pragma unroll
                for (int nt = 0; nt < 4; nt++) {
                    const int jr = nc + nt * 8 + gid;
                    const float b0 = Ks[jr * KST + k0 + tig];
                    const float b1 = Ks[jr * KST + k0 + tig + 4];
#pragma unroll
                    for (int m = 0; m < 2; m++)
                        mma8f(sacc[m][nt],
                              __uint_as_float(qa[m][kt][0]), __uint_as_float(qa[m][kt][1]),
                              __uint_as_float(qa[m][kt][2]), __uint_as_float(qa[m][kt][3]),
                              b0, b1);
                }
            }
            __syncthreads();   // Rs new block visible to all warps

            // gather (pre-scaled) + mask on diagonal; per-half per-m softmax
#pragma unroll
            for (int m = 0; m < 2; m++) {
                const int r0l = mr + m * 16 + gid, r1l = r0l + 8;
                float mt0 = NEGINF, mt1 = NEGINF;
#pragma unroll
                for (int nt = 0; nt < 4; nt++) {
                    const int c0 = nc + nt * 8 + 2 * tig, c1 = c0 + 1;
                    float s00 = sacc[m][nt].x + sm[OFF_RS + r0l * RST + ((diff + r0l - c0) & 127)];
                    float s01 = sacc[m][nt].y + sm[OFF_RS + r0l * RST + ((diff + r0l - c1) & 127)];
                    float s10 = sacc[m][nt].z + sm[OFF_RS + r1l * RST + ((diff + r1l - c0) & 127)];
                    float s11 = sacc[m][nt].w + sm[OFF_RS + r1l * RST + ((diff + r1l - c1) & 127)];
                    if (s == 0) {
                        if (c0 > r0l) s00 = NEGINF;
                        if (c1 > r0l) s01 = NEGINF;
                        if (c0 > r1l) s10 = NEGINF;
                        if (c1 > r1l) s11 = NEGINF;
                    }
                    sacc[m][nt] = make_float4(s00, s01, s10, s11);
                    mt0 = fmaxf(mt0, fmaxf(s00, s01));
                    mt1 = fmaxf(mt1, fmaxf(s10, s11));
                }
                mt0 = fmaxf(mt0, __shfl_xor_sync(FULL, mt0, 1));
                mt0 = fmaxf(mt0, __shfl_xor_sync(FULL, mt0, 2));
                mt1 = fmaxf(mt1, __shfl_xor_sync(FULL, mt1, 1));
                mt1 = fmaxf(mt1, __shfl_xor_sync(FULL, mt1, 2));
                const float mn0 = fmaxf(ma[m][0], mt0);
                const float mn1 = fmaxf(ma[m][1], mt1);

                float sum0 = 0.f, sum1 = 0.f;
#pragma unroll
                for (int nt = 0; nt < 4; nt++) {
                    const float p00 = cvt_tf32(__expf(sacc[m][nt].x - mn0));
                    const float p01 = cvt_tf32(__expf(sacc[m][nt].y - mn0));
                    const float p10 = cvt_tf32(__expf(sacc[m][nt].z - mn1));
                    const float p11 = cvt_tf32(__expf(sacc[m][nt].w - mn1));
                    sum0 += p00 + p01;
                    sum1 += p10 + p11;
                    sacc[m][nt] = make_float4(p00, p01, p10, p11);
                }
                sum0 += __shfl_xor_sync(FULL, sum0, 1);
                sum0 += __shfl_xor_sync(FULL, sum0, 2);
                sum1 += __shfl_xor_sync(FULL, sum1, 1);
                sum1 += __shfl_xor_sync(FULL, sum1, 2);
                const float corr0 = __expf(ma[m][0] - mn0);
                const float corr1 = __expf(ma[m][1] - mn1);
                ma[m][0] = mn0; ma[m][1] = mn1;
                la[m][0] = la[m][0] * corr0 + sum0;
                la[m][1] = la[m][1] * corr1 + sum1;
#pragma unroll
                for (int nt = 0; nt < 8; nt++) {
                    oacc[m][nt].x *= corr0; oacc[m][nt].y *= corr0;
                    oacc[m][nt].z *= corr1; oacc[m][nt].w *= corr1;
                }
            }

            // O += P @ V (own j-half, all 64 h); B-frags reused across m
#pragma unroll
            for (int kt = 0; kt < 4; kt++) {
                float A0[2], A1[2], A2[2], A3[2];
#pragma unroll
                for (int m = 0; m < 2; m++) {
                    const float p00 = sacc[m][kt].x, p01 = sacc[m][kt].y;
                    const float p10 = sacc[m][kt].z, p11 = sacc[m][kt].w;
                    const float e0 = __shfl_sync(FULL, p00, srcA);
                    const float e1 = __shfl_sync(FULL, p01, srcA);
                    const float f0 = __shfl_sync(FULL, p00, srcB);
                    const float f1 = __shfl_sync(FULL, p01, srcB);
                    const float g0 = __shfl_sync(FULL, p10, srcA);
                    const float g1 = __shfl_sync(FULL, p11, srcA);
                    const float h0 = __shfl_sync(FULL, p10, srcB);
                    const float h1 = __shfl_sync(FULL, p11, srcB);
                    A0[m] = oddt ? e1 : e0;
                    A1[m] = oddt ? g1 : g0;
                    A2[m] = oddt ? f1 : f0;
                    A3[m] = oddt ? h1 : h0;
                }
                const int kr0 = nc + kt * 8 + tig;
#pragma unroll
                for (int nto = 0; nto < 8; nto++) {
                    const int hcol = nto * 8 + gid;
                    const float b0 = Ks[kr0 * KST + hcol];
                    const float b1 = Ks[(kr0 + 4) * KST + hcol];
#pragma unroll
                    for (int m = 0; m < 2; m++)
                        mma8f(oacc[m][nto], A0[m], A1[m], A2[m], A3[m], b0, b1);
                }
            }
        }

        // ---- item epilogue: LSE-combine the two j-halves via smem scratch ----
        __syncthreads();   // all PV reads of Ks/Rs done; reuse Rs as scratch
#pragma unroll
        for (int m = 0; m < 2; m++) {
            const int rw = mr + m * 16 + gid;
#pragma unroll
            for (int nto = 0; nto < 8; nto++) {
                const int col = nto * 8 + 2 * tig;
                *(float2*)(sm + OFF_RS + wc * 4096 + rw * 64 + col) =
                    make_float2(oacc[m][nto].x, oacc[m][nto].y);
                *(float2*)(sm + OFF_RS + wc * 4096 + (rw + 8) * 64 + col) =
                    make_float2(oacc[m][nto].z, oacc[m][nto].w);
            }
            if (tig == 0) {
                sm[OFF_LP + wc * 64 + rw] = la[m][0];
                sm[OFF_LP + wc * 64 + rw + 8] = la[m][1];
                sm[OFF_MM + wc * 64 + rw] = ma[m][0];
                sm[OFF_MM + wc * 64 + rw + 8] = ma[m][1];
            }
        }
        __syncthreads();

        if (wc == 0) {
            const int slot = (b * 32 + ib) * 4 + chunk;
            float* po = g_pO + (size_t)slot * 4096;
            float* pml = g_pml + (size_t)slot * 128;
            {
                const int row = mr + lane;   // 32 lanes <-> 32 rows
                const float mA = sm[OFF_MM + row], mB = sm[OFF_MM + 64 + row];
                const float M = fmaxf(mA, mB);
                const float wA = __expf(mA - M), wB = __expf(mB - M);
                const float L = wA * sm[OFF_LP + row] + wB * sm[OFF_LP + 64 + row];
                sm[OFF_WA + row] = wA;
                sm[OFF_WB + row] = wB;
                sm[OFF_IV + row] = 1.0f / L;
                if (nch > 1) {
                    pml[row] = M;
                    pml[64 + row] = L;
                }
            }
            __syncwarp();
#pragma unroll
            for (int it = 0; it < 16; it++) {
                const int idx = lane + it * 32;   // 512 float4 over 32 rows
                const int rl = idx >> 4, c4 = idx & 15;
                const int row = mr + rl;
                const float4 A = *(const float4*)(sm + OFF_RS + row * 64 + c4 * 4);
                const float4 Bv = *(const float4*)(sm + OFF_RS + 4096 + row * 64 + c4 * 4);
                const float wA = sm[OFF_WA + row], wB = sm[OFF_WB + row];
                const float vx = wA * A.x + wB * Bv.x;
                const float vy = wA * A.y + wB * Bv.y;
                const float vz = wA * A.z + wB * Bv.z;
                const float vw = wA * A.w + wB * Bv.w;
                if (nch == 1) {
                    const float inv = sm[OFF_IV + row];
                    *(float4*)(out + ((size_t)b * Tt + i0 + row) * Hh + c4 * 4) =
                        make_float4(vx * inv, vy * inv, vz * inv, vw * inv);
                } else {
                    *(float4*)(po + row * 64 + c4 * 4) = make_float4(vx, vy, vz, vw);
                }
            }
        }
    }
}

// ---------------------------------------------------------------------------
// Kernel 3: merge split-j partials (ib >= 8 only); nch slots per (b,ib).
// ---------------------------------------------------------------------------
__global__ void __launch_bounds__(256) merge_kernel(float* __restrict__ out) {
    __shared__ float swgt[4][16];
    __shared__ float sinv[16];

    const int blk = blockIdx.x;             // 0..767
    const int itemi = blk >> 2, qtr = blk & 3;
    const int b = itemi / 24;
    const int ib = 8 + itemi % 24;
    const int nch = (ib >> 3) + 1;
    const int tid = threadIdx.x;
    const float* pml = g_pml + (size_t)((b * 32 + ib) * 4) * 128;
    const float* po = g_pO + (size_t)((b * 32 + ib) * 4) * 4096;
    float* ob = out + ((size_t)b * Tt + ib * 64) * Hh;

    if (tid < 16) {
        const int row = qtr * 16 + tid;
        float M = -1e30f;
        for (int c = 0; c < nch; c++) M = fmaxf(M, pml[c * 128 + row]);
        float L = 0.f;
        for (int c = 0; c < nch; c++) {
            const float w = __expf(pml[c * 128 + row] - M);
            swgt[c][tid] = w;
            L += w * pml[c * 128 + 64 + row];
        }
        sinv[tid] = 1.0f / L;
    }
    __syncthreads();

    const int rl = tid >> 4, c4 = tid & 15;
    const int row = qtr * 16 + rl;
    float4 v = make_float4(0.f, 0.f, 0.f, 0.f);
    for (int c = 0; c < nch; c++) {
        const float w = swgt[c][rl];
        const float4 p = *(const float4*)(po + (size_t)c * 4096 + row * 64 + c4 * 4);
        v.x += w * p.x; v.y += w * p.y; v.z += w * p.z; v.w += w * p.w;
    }
    const float inv = sinv[rl];
    *(float4*)(ob + (size_t)row * Hh + c4 * 4) =
        make_float4(v.x * inv, v.y * inv, v.z * inv, v.w * inv);
}

// ---------------------------------------------------------------------------
extern "C" void kernel_launch(void* const* d_in, const int* in_sizes, int n_in,
                              void* d_out, int out_size) {
    const float* x  = (const float*)d_in[0];   // [8, 2048, 1024]
    const float* Wq = (const float*)d_in[1];   // [1024, 64]
    const float* E  = (const float*)d_in[2];   // [2048, 64]
    float* out = (float*)d_out;                // [8, 2048, 64]

    cudaFuncSetAttribute(qgemm_tf32, cudaFuncAttributeMaxDynamicSharedMemorySize,
                         QGEMM_SMEM_BYTES);
    cudaFuncSetAttribute(attn_mma, cudaFuncAttributeMaxDynamicSharedMemorySize,
                         ATTN_SMEM_BYTES);

    wconv_kernel<<<(Tt * Hh + 255) / 256, 256>>>(Wq, E);
    qgemm_tf32<<<(Bb * Tt) / 64, 256, QGEMM_SMEM_BYTES>>>(x);   // grid 256
    attn_mma<<<296, 128, ATTN_SMEM_BYTES>>>(out);
    merge_kernel<<<768, 256>>>(out);
}

// round 17
// speedup vs baseline: 1.1216x; 1.1070x over previous
#include <cuda_runtime.h>
#include <cuda_bf16.h>
#include <cstdint>

#define Bb 8
#define Tt 2048
#define Cc 1024
#define Hh 64
#define NCHUNK_ITEMS 640   // (b, ib, j-chunk) items, chunks of <=8 j-tiles

__device__ float g_q[Bb * Tt * Hh];          // tf32-rounded q
__device__ uint32_t g_wph[(Cc / 2) * Hh];    // packed bf16x2 W hi (k-pairs)
__device__ uint32_t g_wpl[(Cc / 2) * Hh];    // packed bf16x2 W lo
__device__ float g_er[Tt * Hh];              // g_er[d][h] = tf32(E[T-1-d][h])
__device__ float g_pO[8 * 32 * 4 * 64 * 64];
__device__ float g_pml[8 * 32 * 4 * 128];    // [m(64) | l(64)] per chunk slot
__device__ int g_ctr;

__device__ __forceinline__ float cvt_tf32(float x) {
    uint32_t r;
    asm("cvt.rna.tf32.f32 %0, %1;" : "=r"(r) : "f"(x));
    return __uint_as_float(r);
}

__device__ __forceinline__ void mma8(float4& d, uint32_t a0, uint32_t a1,
                                     uint32_t a2, uint32_t a3,
                                     uint32_t b0, uint32_t b1) {
    asm volatile(
        "mma.sync.aligned.m16n8k8.row.col.f32.tf32.tf32.f32 "
        "{%0,%1,%2,%3}, {%4,%5,%6,%7}, {%8,%9}, {%0,%1,%2,%3};"
        : "+f"(d.x), "+f"(d.y), "+f"(d.z), "+f"(d.w)
        : "r"(a0), "r"(a1), "r"(a2), "r"(a3), "r"(b0), "r"(b1));
}

__device__ __forceinline__ void mma8f(float4& d, float a0, float a1,
                                      float a2, float a3, float b0, float b1) {
    mma8(d, __float_as_uint(a0), __float_as_uint(a1), __float_as_uint(a2),
         __float_as_uint(a3), __float_as_uint(b0), __float_as_uint(b1));
}

__device__ __forceinline__ void mma16bf(float4& d, uint32_t a0, uint32_t a1,
                                        uint32_t a2, uint32_t a3,
                                        uint32_t b0, uint32_t b1) {
    asm volatile(
        "mma.sync.aligned.m16n8k16.row.col.f32.bf16.bf16.f32 "
        "{%0,%1,%2,%3}, {%4,%5,%6,%7}, {%8,%9}, {%0,%1,%2,%3};"
        : "+f"(d.x), "+f"(d.y), "+f"(d.z), "+f"(d.w)
        : "r"(a0), "r"(a1), "r"(a2), "r"(a3), "r"(b0), "r"(b1));
}

__device__ __forceinline__ void cp16(uint32_t smem_dst, const float* gsrc) {
    asm volatile("cp.async.ca.shared.global [%0], [%1], 16;\n"
                 :: "r"(smem_dst), "l"(gsrc));
}

// ---------------------------------------------------------------------------
// Kernel 0: pack Wq into bf16x2 hi/lo k-pairs; build reversed tf32 E table.
// ---------------------------------------------------------------------------
__global__ void wconv_kernel(const float* __restrict__ w,
                             const float* __restrict__ E) {
    const int i = blockIdx.x * 256 + threadIdx.x;
    if (i < (Cc / 2) * Hh) {
        const int p = i >> 6, n = i & 63;      // pair row, col
        const float v0 = w[(size_t)(2 * p) * Hh + n];
        const float v1 = w[(size_t)(2 * p + 1) * Hh + n];
        __nv_bfloat162 h = __floats2bfloat162_rn(v0, v1);   // low=v0, high=v1
        const float2 hf = __bfloat1622float2(h);
        __nv_bfloat162 l = __floats2bfloat162_rn(v0 - hf.x, v1 - hf.y);
        g_wph[i] = *(const uint32_t*)&h;
        g_wpl[i] = *(const uint32_t*)&l;
    }
    if (i < Tt * Hh) {
        const int d = i >> 6, hcol = i & 63;
        g_er[i] = cvt_tf32(E[(size_t)(Tt - 1 - d) * Hh + hcol]);
    }
}

// ---------------------------------------------------------------------------
// Kernel 1: q = x @ Wq via bf16x3 (split bf16, 2x tensor rate vs tf32).
// BM=64, grid 256, cp.async double-buffered. Epilogue stores q tf32-rounded.
// smem: Xs[2][64][36] f32, Wh[2][16][72] u32, Wl[2][16][72] u32 = 36.9 KB
// ---------------------------------------------------------------------------
#define QS_XS(st)  ((st) * 2304)            // 64*36 words
#define QS_WH(st)  (4608 + (st) * 1152)     // 16*72 words
#define QS_WL(st)  (6912 + (st) * 1152)
#define QGEMM_SMEM_BYTES (9216 * 4)

__global__ void __launch_bounds__(256, 2) qgemm_bf16(const float* __restrict__ x) {
    extern __shared__ float qs[];
    uint32_t* qsu = (uint32_t*)qs;
    const int tid = threadIdx.x;
    if (blockIdx.x == 0 && tid == 0) g_ctr = 0;   // reset for attn work-steal

    const int wid = tid >> 5, lane = tid & 31;
    const int gid = lane >> 2, tig = lane & 3;
    const int wr = wid & 3, wc = wid >> 2;
    const int r0 = blockIdx.x * 64;
    const uint32_t sbase = (uint32_t)__cvta_generic_to_shared(qs);

    auto issue_load = [&](int kb, int st) {
        const int k0g = kb * 32;
#pragma unroll
        for (int it = 0; it < 2; it++) {
            const int idx = tid + it * 256;     // 512 float4
            const int row = idx >> 3, c4 = idx & 7;
            cp16(sbase + (QS_XS(st) + row * 36 + c4 * 4) * 4,
                 x + (size_t)(r0 + row) * Cc + k0g + c4 * 4);
        }
        {   // W hi: 16 pair-rows x 16 uint4 groups = 256 threads exactly
            const int row = tid >> 4, c4 = tid & 15;
            cp16(sbase + (QS_WH(st) + row * 72 + c4 * 4) * 4,
                 (const float*)(g_wph + (size_t)(k0g / 2 + row) * Hh + c4 * 4));
            cp16(sbase + (QS_WL(st) + row * 72 + c4 * 4) * 4,
                 (const float*)(g_wpl + (size_t)(k0g / 2 + row) * Hh + c4 * 4));
        }
    };

    float4 acc[4] = {};

    issue_load(0, 0);
    asm volatile("cp.async.commit_group;\n");

    for (int kb = 0; kb < Cc / 32; kb++) {
        if (kb + 1 < Cc / 32) {
            issue_load(kb + 1, (kb + 1) & 1);
            asm volatile("cp.async.commit_group;\n");
            asm volatile("cp.async.wait_group 1;\n");
        } else {
            asm volatile("cp.async.wait_group 0;\n");
        }
        __syncthreads();

        const float* Xs = qs + QS_XS(kb & 1);
        const uint32_t* Wh = qsu + QS_WH(kb & 1);
        const uint32_t* Wl = qsu + QS_WL(kb & 1);

#pragma unroll
        for (int kt = 0; kt < 2; kt++) {        // two k16 steps per K32 block
            const int k0 = kt * 16;
            uint32_t ah[4], al[4];
#pragma unroll
            for (int p = 0; p < 4; p++) {
                const int row = wr * 16 + gid + (p & 1) * 8;
                const int kk = k0 + (p >> 1) * 8 + 2 * tig;
                const float2 v = *(const float2*)&Xs[row * 36 + kk];
                __nv_bfloat162 h = __floats2bfloat162_rn(v.x, v.y);
                const float2 hf = __bfloat1622float2(h);
                __nv_bfloat162 l = __floats2bfloat162_rn(v.x - hf.x, v.y - hf.y);
                ah[p] = *(const uint32_t*)&h;
                al[p] = *(const uint32_t*)&l;
            }
#pragma unroll
            for (int nt = 0; nt < 4; nt++) {
                const int ncol = wc * 32 + nt * 8 + gid;
                const int pr0 = kt * 8 + tig;   // pair row within block
                const uint32_t bh0 = Wh[pr0 * 72 + ncol];
                const uint32_t bh1 = Wh[(pr0 + 4) * 72 + ncol];
                const uint32_t bl0 = Wl[pr0 * 72 + ncol];
                const uint32_t bl1 = Wl[(pr0 + 4) * 72 + ncol];
                mma16bf(acc[nt], ah[0], ah[1], ah[2], ah[3], bh0, bh1);
                mma16bf(acc[nt], al[0], al[1], al[2], al[3], bh0, bh1);
                mma16bf(acc[nt], ah[0], ah[1], ah[2], ah[3], bl0, bl1);
            }
        }
        __syncthreads();
    }

#pragma unroll
    for (int nt = 0; nt < 4; nt++) {
        const int row = r0 + wr * 16 + gid;
        const int col = wc * 32 + nt * 8 + 2 * tig;
        *(float2*)(g_q + (size_t)row * Hh + col) =
            make_float2(cvt_tf32(acc[nt].x), cvt_tf32(acc[nt].y));
        *(float2*)(g_q + (size_t)(row + 8) * Hh + col) =
            make_float2(cvt_tf32(acc[nt].z), cvt_tf32(acc[nt].w));
    }
}

// ---------------------------------------------------------------------------
// Kernel 2: causal flash attention + rel bias (exact R13 config, best known).
// ---------------------------------------------------------------------------
#define KST 68
#define RST 132
#define OFF_KS0 0
#define OFF_KS1 4352
#define OFF_EB0 8704
#define OFF_EB1 13056
#define OFF_RS  17408
#define OFF_LP  25856
#define OFF_MM  25984
#define OFF_WA  26112
#define OFF_WB  26176
#define OFF_IV  26240
#define SMEMF   26304
#define ATTN_SMEM_BYTES (SMEMF * 4)
#define NEGINF __int_as_float(0xff800000)

__global__ void __launch_bounds__(128, 2) attn_mma(float* __restrict__ out) {
    extern __shared__ float sm[];
    __shared__ int s_item;

    const int tid = threadIdx.x;
    const int wid = tid >> 5, lane = tid & 31;
    const int gid = lane >> 2, tig = lane & 3;
    const int wr = wid & 1, wc = wid >> 1;
    const int mr = wr * 32;
    const int nc = wc * 32;
    const uint32_t sbase = (uint32_t)__cvta_generic_to_shared(sm);
    const unsigned FULL = 0xffffffffu;
    const int srcA = (lane & ~3) | (tig >> 1);
    const int srcB = srcA + 2;
    const bool oddt = (tig & 1);

    while (true) {
        __syncthreads();
        if (tid == 0) s_item = atomicAdd(&g_ctr, 1);
        __syncthreads();
        const int item = s_item;
        if (item >= NCHUNK_ITEMS) return;

        const int b = item & 7;
        int t = item >> 3;
        int ib = 31;
        while (true) {
            const int n = (ib >> 3) + 1;
            if (t < n) break;
            t -= n;
            ib--;
        }
        const int chunk = t;
        const int s0c = chunk * 8;
        const int s1c = min(s0c + 7, ib);
        const int nch = (ib >> 3) + 1;
        const int i0 = ib * 64;
        const float* qb = g_q + (size_t)b * (Tt * Hh);

        auto issue_tile = [&](int s) {
            const int j0t = (ib - s) * 64;
            const int dft = s * 64;
            const uint32_t kdst = sbase + (OFF_KS0 + (s & 1) * 4352) * 4;
            const uint32_t edst = sbase + (OFF_EB0 + (s & 1) * 4352) * 4;
#pragma unroll
            for (int it = 0; it < 8; it++) {
                const int idx = tid + it * 128;
                const int row = idx >> 4, c4 = idx & 15;
                cp16(kdst + (row * KST + c4 * 4) * 4,
                     qb + (size_t)(j0t + row) * Hh + c4 * 4);
                cp16(edst + (row * KST + c4 * 4) * 4,
                     g_er + (size_t)(dft + row) * Hh + c4 * 4);
            }
            asm volatile("cp.async.commit_group;\n");
        };

        issue_tile(s0c);   // prefetch first tile

        // Q fragments -> registers, pre-scaled by H^-0.5 (exact pow2 in tf32)
        uint32_t qa[2][8][4];
#pragma unroll
        for (int m = 0; m < 2; m++) {
            const int row0 = i0 + mr + m * 16 + gid;
#pragma unroll
            for (int kt = 0; kt < 8; kt++) {
                const int k0 = kt * 8 + tig;
                qa[m][kt][0] = __float_as_uint(0.125f * qb[(size_t)row0 * Hh + k0]);
                qa[m][kt][1] = __float_as_uint(0.125f * qb[(size_t)(row0 + 8) * Hh + k0]);
                qa[m][kt][2] = __float_as_uint(0.125f * qb[(size_t)row0 * Hh + k0 + 4]);
                qa[m][kt][3] = __float_as_uint(0.125f * qb[(size_t)(row0 + 8) * Hh + k0 + 4]);
            }
        }

        if (s0c == 0) {
            // zero ring cols 64..127 (covers dg<0 at the diagonal tile)
#pragma unroll
            for (int it = 0; it < 8; it++) {
                const int idx = tid + it * 128;
                const int row = idx >> 4, c4 = idx & 15;
                *(float4*)(sm + OFF_RS + row * RST + 64 + c4 * 4) =
                    make_float4(0.f, 0.f, 0.f, 0.f);
            }
        } else {
            // prologue R block for diffp = (s0c-1)*64; E from g_er (one-time)
            const int diffp = (s0c - 1) * 64;
            float4 racc[2][4] = {};
#pragma unroll
            for (int kt = 0; kt < 8; kt++) {
                const int k0 = kt * 8;
#pragma unroll
                for (int nt = 0; nt < 4; nt++) {
                    const int rr = nc + nt * 8 + gid;
                    const float* er = g_er + (size_t)(diffp + rr) * Hh;
                    const float b0 = er[k0 + tig], b1 = er[k0 + tig + 4];
#pragma unroll
                    for (int m = 0; m < 2; m++)
                        mma8f(racc[m][nt],
                              __uint_as_float(qa[m][kt][0]), __uint_as_float(qa[m][kt][1]),
                              __uint_as_float(qa[m][kt][2]), __uint_as_float(qa[m][kt][3]),
                              b0, b1);
                }
            }
            const int rb = diffp & 127;   // = 64
#pragma unroll
            for (int m = 0; m < 2; m++)
#pragma unroll
                for (int nt = 0; nt < 4; nt++) {
                    const int colr = rb + nc + nt * 8 + 2 * tig;
                    const int rw = mr + m * 16 + gid;
                    *(float2*)(sm + OFF_RS + rw * RST + colr) =
                        make_float2(racc[m][nt].x, racc[m][nt].y);
                    *(float2*)(sm + OFF_RS + (rw + 8) * RST + colr) =
                        make_float2(racc[m][nt].z, racc[m][nt].w);
                }
        }

        float4 oacc[2][8] = {};
        float ma[2][2] = {{-1e30f, -1e30f}, {-1e30f, -1e30f}};
        float la[2][2] = {{0.f, 0.f}, {0.f, 0.f}};

        for (int s = s0c; s <= s1c; s++) {
            const int diff = 64 * s;

            asm volatile("cp.async.wait_group 0;\n");
            __syncthreads();   // tile buffers visible; prev-tile readers done
            if (s < s1c) issue_tile(s + 1);

            const float* Ks = sm + ((s & 1) ? OFF_KS1 : OFF_KS0);
            const float* Eb = sm + ((s & 1) ? OFF_EB1 : OFF_EB0);

            // R (new 64 dg cols; warp: rows mr..+31 x cols nc..+31)
            float4 racc[2][4] = {};
#pragma unroll
            for (int kt = 0; kt < 8; kt++) {
                const int k0 = kt * 8;
#pragma unroll
                for (int nt = 0; nt < 4; nt++) {
                    const int rr = nc + nt * 8 + gid;
                    const float b0 = Eb[rr * KST + k0 + tig];
                    const float b1 = Eb[rr * KST + k0 + tig + 4];
#pragma unroll
                    for (int m = 0; m < 2; m++)
                        mma8f(racc[m][nt],
                              __uint_as_float(qa[m][kt][0]), __uint_as_float(qa[m][kt][1]),
                              __uint_as_float(qa[m][kt][2]), __uint_as_float(qa[m][kt][3]),
                              b0, b1);
                }
            }
            {
                const int rb = diff & 127;
#pragma unroll
                for (int m = 0; m < 2; m++)
#pragma unroll
                    for (int nt = 0; nt < 4; nt++) {
                        const int colr = rb + nc + nt * 8 + 2 * tig;
                        const int rw = mr + m * 16 + gid;
                        *(float2*)(sm + OFF_RS + rw * RST + colr) =
                            make_float2(racc[m][nt].x, racc[m][nt].y);
                        *(float2*)(sm + OFF_RS + (rw + 8) * RST + colr) =
                            make_float2(racc[m][nt].z, racc[m][nt].w);
                    }
            }

            // S = Q @ K^T (own j-half; B-frags reused across both m)
            float4 sacc[2][4] = {};
#pragma unroll
            for (int kt = 0; kt < 8; kt++) {
                const int k0 = kt * 8;
#pragma unroll
                for (int nt = 0; nt < 4; nt++) {
                    const int jr = nc + nt * 8 + gid;
                    const float b0 = Ks[jr * KST + k0 + tig];
                    const float b1 = Ks[jr * KST + k0 + tig + 4];
#pragma unroll
                    for (int m = 0; m < 2; m++)
                        mma8f(sacc[m][nt],
                              __uint_as_float(qa[m][kt][0]), __uint_as_float(qa[m][kt][1]),
                              __uint_as_float(qa[m][kt][2]), __uint_as_float(qa[m][kt][3]),
                              b0, b1);
                }
            }
            __syncthreads();   // Rs new block visible to all warps

            // gather (pre-scaled) + mask on diagonal; per-half per-m softmax
#pragma unroll
            for (int m = 0; m < 2; m++) {
                const int r0l = mr + m * 16 + gid, r1l = r0l + 8;
                float mt0 = NEGINF, mt1 = NEGINF;
#pragma unroll
                for (int nt = 0; nt < 4; nt++) {
                    const int c0 = nc + nt * 8 + 2 * tig, c1 = c0 + 1;
                    float s00 = sacc[m][nt].x + sm[OFF_RS + r0l * RST + ((diff + r0l - c0) & 127)];
                    float s01 = sacc[m][nt].y + sm[OFF_RS + r0l * RST + ((diff + r0l - c1) & 127)];
                    float s10 = sacc[m][nt].z + sm[OFF_RS + r1l * RST + ((diff + r1l - c0) & 127)];
                    float s11 = sacc[m][nt].w + sm[OFF_RS + r1l * RST + ((diff + r1l - c1) & 127)];
                    if (s == 0) {
                        if (c0 > r0l) s00 = NEGINF;
                        if (c1 > r0l) s01 = NEGINF;
                        if (c0 > r1l) s10 = NEGINF;
                        if (c1 > r1l) s11 = NEGINF;
                    }
                    sacc[m][nt] = make_float4(s00, s01, s10, s11);
                    mt0 = fmaxf(mt0, fmaxf(s00, s01));
                    mt1 = fmaxf(mt1, fmaxf(s10, s11));
                }
                mt0 = fmaxf(mt0, __shfl_xor_sync(FULL, mt0, 1));
                mt0 = fmaxf(mt0, __shfl_xor_sync(FULL, mt0, 2));
                mt1 = fmaxf(mt1, __shfl_xor_sync(FULL, mt1, 1));
                mt1 = fmaxf(mt1, __shfl_xor_sync(FULL, mt1, 2));
                const float mn0 = fmaxf(ma[m][0], mt0);
                const float mn1 = fmaxf(ma[m][1], mt1);

                float sum0 = 0.f, sum1 = 0.f;
#pragma unroll
                for (int nt = 0; nt < 4; nt++) {
                    const float p00 = cvt_tf32(__expf(sacc[m][nt].x - mn0));
                    const float p01 = cvt_tf32(__expf(sacc[m][nt].y - mn0));
                    const float p10 = cvt_tf32(__expf(sacc[m][nt].z - mn1));
                    const float p11 = cvt_tf32(__expf(sacc[m][nt].w - mn1));
                    sum0 += p00 + p01;
                    sum1 += p10 + p11;
                    sacc[m][nt] = make_float4(p00, p01, p10, p11);
                }
                sum0 += __shfl_xor_sync(FULL, sum0, 1);
                sum0 += __shfl_xor_sync(FULL, sum0, 2);
                sum1 += __shfl_xor_sync(FULL, sum1, 1);
                sum1 += __shfl_xor_sync(FULL, sum1, 2);
                const float corr0 = __expf(ma[m][0] - mn0);
                const float corr1 = __expf(ma[m][1] - mn1);
                ma[m][0] = mn0; ma[m][1] = mn1;
                la[m][0] = la[m][0] * corr0 + sum0;
                la[m][1] = la[m][1] * corr1 + sum1;
#pragma unroll
                for (int nt = 0; nt < 8; nt++) {
                    oacc[m][nt].x *= corr0; oacc[m][nt].y *= corr0;
                    oacc[m][nt].z *= corr1; oacc[m][nt].w *= corr1;
                }
            }

            // O += P @ V (own j-half, all 64 h); B-frags reused across m
#pragma unroll
            for (int kt = 0; kt < 4; kt++) {
                float A0[2], A1[2], A2[2], A3[2];
#pragma unroll
                for (int m = 0; m < 2; m++) {
                    const float p00 = sacc[m][kt].x, p01 = sacc[m][kt].y;
                    const float p10 = sacc[m][kt].z, p11 = sacc[m][kt].w;
                    const float e0 = __shfl_sync(FULL, p00, srcA);
                    const float e1 = __shfl_sync(FULL, p01, srcA);
                    const float f0 = __shfl_sync(FULL, p00, srcB);
                    const float f1 = __shfl_sync(FULL, p01, srcB);
                    const float g0 = __shfl_sync(FULL, p10, srcA);
                    const float g1 = __shfl_sync(FULL, p11, srcA);
                    const float h0 = __shfl_sync(FULL, p10, srcB);
                    const float h1 = __shfl_sync(FULL, p11, srcB);
                    A0[m] = oddt ? e1 : e0;
                    A1[m] = oddt ? g1 : g0;
                    A2[m] = oddt ? f1 : f0;
                    A3[m] = oddt ? h1 : h0;
                }
                const int kr0 = nc + kt * 8 + tig;
#pragma unroll
                for (int nto = 0; nto < 8; nto++) {
                    const int hcol = nto * 8 + gid;
                    const float b0 = Ks[kr0 * KST + hcol];
                    const float b1 = Ks[(kr0 + 4) * KST + hcol];
#pragma unroll
                    for (int m = 0; m < 2; m++)
                        mma8f(oacc[m][nto], A0[m], A1[m], A2[m], A3[m], b0, b1);
                }
            }
        }

        // ---- item epilogue: LSE-combine the two j-halves via smem scratch ----
        __syncthreads();   // all PV reads of Ks/Rs done; reuse Rs as scratch
#pragma unroll
        for (int m = 0; m < 2; m++) {
            const int rw = mr + m * 16 + gid;
#pragma unroll
            for (int nto = 0; nto < 8; nto++) {
                const int col = nto * 8 + 2 * tig;
                *(float2*)(sm + OFF_RS + wc * 4096 + rw * 64 + col) =
                    make_float2(oacc[m][nto].x, oacc[m][nto].y);
                *(float2*)(sm + OFF_RS + wc * 4096 + (rw + 8) * 64 + col) =
                    make_float2(oacc[m][nto].z, oacc[m][nto].w);
            }
            if (tig == 0) {
                sm[OFF_LP + wc * 64 + rw] = la[m][0];
                sm[OFF_LP + wc * 64 + rw + 8] = la[m][1];
                sm[OFF_MM + wc * 64 + rw] = ma[m][0];
                sm[OFF_MM + wc * 64 + rw + 8] = ma[m][1];
            }
        }
        __syncthreads();

        if (wc == 0) {
            const int slot = (b * 32 + ib) * 4 + chunk;
            float* po = g_pO + (size_t)slot * 4096;
            float* pml = g_pml + (size_t)slot * 128;
            {
                const int row = mr + lane;
                const float mA = sm[OFF_MM + row], mB = sm[OFF_MM + 64 + row];
                const float M = fmaxf(mA, mB);
                const float wA = __expf(mA - M), wB = __expf(mB - M);
                const float L = wA * sm[OFF_LP + row] + wB * sm[OFF_LP + 64 + row];
                sm[OFF_WA + row] = wA;
                sm[OFF_WB + row] = wB;
                sm[OFF_IV + row] = 1.0f / L;
                if (nch > 1) {
                    pml[row] = M;
                    pml[64 + row] = L;
                }
            }
            __syncwarp();
#pragma unroll
            for (int it = 0; it < 16; it++) {
                const int idx = lane + it * 32;
                const int rl = idx >> 4, c4 = idx & 15;
                const int row = mr + rl;
                const float4 A = *(const float4*)(sm + OFF_RS + row * 64 + c4 * 4);
                const float4 Bv = *(const float4*)(sm + OFF_RS + 4096 + row * 64 + c4 * 4);
                const float wA = sm[OFF_WA + row], wB = sm[OFF_WB + row];
                const float vx = wA * A.x + wB * Bv.x;
                const float vy = wA * A.y + wB * Bv.y;
                const float vz = wA * A.z + wB * Bv.z;
                const float vw = wA * A.w + wB * Bv.w;
                if (nch == 1) {
                    const float inv = sm[OFF_IV + row];
                    *(float4*)(out + ((size_t)b * Tt + i0 + row) * Hh + c4 * 4) =
                        make_float4(vx * inv, vy * inv, vz * inv, vw * inv);
                } else {
                    *(float4*)(po + row * 64 + c4 * 4) = make_float4(vx, vy, vz, vw);
                }
            }
        }
    }
}

// ---------------------------------------------------------------------------
// Kernel 3: merge split-j partials (ib >= 8 only); nch slots per (b,ib).
// ---------------------------------------------------------------------------
__global__ void __launch_bounds__(256) merge_kernel(float* __restrict__ out) {
    __shared__ float swgt[4][16];
    __shared__ float sinv[16];

    const int blk = blockIdx.x;             // 0..767
    const int itemi = blk >> 2, qtr = blk & 3;
    const int b = itemi / 24;
    const int ib = 8 + itemi % 24;
    const int nch = (ib >> 3) + 1;
    const int tid = threadIdx.x;
    const float* pml = g_pml + (size_t)((b * 32 + ib) * 4) * 128;
    const float* po = g_pO + (size_t)((b * 32 + ib) * 4) * 4096;
    float* ob = out + ((size_t)b * Tt + ib * 64) * Hh;

    if (tid < 16) {
        const int row = qtr * 16 + tid;
        float M = -1e30f;
        for (int c = 0; c < nch; c++) M = fmaxf(M, pml[c * 128 + row]);
        float L = 0.f;
        for (int c = 0; c < nch; c++) {
            const float w = __expf(pml[c * 128 + row] - M);
            swgt[c][tid] = w;
            L += w * pml[c * 128 + 64 + row];
        }
        sinv[tid] = 1.0f / L;
    }
    __syncthreads();

    const int rl = tid >> 4, c4 = tid & 15;
    const int row = qtr * 16 + rl;
    float4 v = make_float4(0.f, 0.f, 0.f, 0.f);
    for (int c = 0; c < nch; c++) {
        const float w = swgt[c][rl];
        const float4 p = *(const float4*)(po + (size_t)c * 4096 + row * 64 + c4 * 4);
        v.x += w * p.x; v.y += w * p.y; v.z += w * p.z; v.w += w * p.w;
    }
    const float inv = sinv[rl];
    *(float4*)(ob + (size_t)row * Hh + c4 * 4) =
        make_float4(v.x * inv, v.y * inv, v.z * inv, v.w * inv);
}

// ---------------------------------------------------------------------------
extern "C" void kernel_launch(void* const* d_in, const int* in_sizes, int n_in,
                              void* d_out, int out_size) {
    const float* x  = (const float*)d_in[0];   // [8, 2048, 1024]
    const float* Wq = (const float*)d_in[1];   // [1024, 64]
    const float* E  = (const float*)d_in[2];   // [2048, 64]
    float* out = (float*)d_out;                // [8, 2048, 64]

    cudaFuncSetAttribute(qgemm_bf16, cudaFuncAttributeMaxDynamicSharedMemorySize,
                         QGEMM_SMEM_BYTES);
    cudaFuncSetAttribute(attn_mma, cudaFuncAttributeMaxDynamicSharedMemorySize,
                         ATTN_SMEM_BYTES);

    wconv_kernel<<<(Tt * Hh + 255) / 256, 256>>>(Wq, E);
    qgemm_bf16<<<(Bb * Tt) / 64, 256, QGEMM_SMEM_BYTES>>>(x);
    attn_mma<<<296, 128, ATTN_SMEM_BYTES>>>(out);
    merge_kernel<<<768, 256>>>(out);
}